// round 8
// baseline (speedup 1.0000x reference)
#include <cuda_runtime.h>
#include <cuda_fp16.h>

#define DEV_INLINE __device__ __forceinline__

// fully-inline erf (Abramowitz-Stegun 7.1.26, |err| <= 1.5e-7) -> exact-gelu
static DEV_INLINE float erf_inline(float x){
    float ax = fabsf(x);
    float t = __frcp_rn(fmaf(0.3275911f, ax, 1.0f));
    float y = fmaf(t, 1.061405429f, -1.453152027f);
    y = fmaf(t, y, 1.421413741f);
    y = fmaf(t, y, -0.284496736f);
    y = fmaf(t, y, 0.254829592f);
    y = y * t;
    float e = __expf(-ax*ax);
    float r = fmaf(-y, e, 1.0f);
    return copysignf(r, x);
}
static DEV_INLINE float gelu_f(float x){
    return 0.5f * x * (1.f + erf_inline(x * 0.70710678118654752440f));
}
static DEV_INLINE float exp_inline(float x){ return __expf(x); }

#define NB 512
#define NO 181
#define NI 96
#define ND 16
#define BOI (NO*NI)   // 17376

// ---------------- scratch (device globals; referenced ONLY from device code) ----------------
__device__ float  g_h1[NB*64*49];                 // conv1 out [b,ic,49]
__device__ float  g_col[1024*8192];               // im2col buffer
__device__ float  g_c2 [128*18432];               // conv2 out [oc, b*36+p]
__device__ float  g_c3 [256*12800];               // conv3 out [oc, b*25+p]
__device__ float  g_cp [96*8192];                 // pc conv out [oc, b*16+p]
__device__ float  g_u  [NB*NI*ND];
__device__ __half g_uhat[(size_t)NB*NO*NI*ND];    // 285 MB (fp16)
__device__ float  g_x  [NB*NO*ND];
__device__ int    g_idx[NB*4];
__device__ float  g_a1[2048*1024];
__device__ float  g_a2[2048*768];
__device__ float  g_a3[2048*512];
__device__ float  g_a4[2048*512];
__device__ float  g_a5[2048*256];

__device__ DEV_INLINE float* g_selbuf(int s){
    switch(s){
        case 0: return g_col;
        case 1: return g_c2;
        case 2: return g_c3;
        case 3: return g_cp;
        case 4: return g_a1;
        case 5: return g_a2;
        case 6: return g_a3;
        case 7: return g_a4;
        case 8: return g_a5;
    }
    return nullptr;
}

// ---------------- conv1: [512,3,8,8] -> gelu -> [512,64,7,7] ----------------
__global__ void __launch_bounds__(256) k_conv1(const float* __restrict__ x,
                                               const float* __restrict__ w,
                                               const float* __restrict__ bias){
    int idx = blockIdx.x*256 + threadIdx.x;
    if (idx >= NB*64*49) return;
    int p = idx % 49; int oc = (idx/49) & 63; int b = idx/(49*64);
    int y = p/7, xx = p%7;
    float acc = bias[oc];
    #pragma unroll
    for (int ci=0; ci<3; ci++){
        const float* xp = x + (b*3+ci)*64 + y*8 + xx;
        const float* wp = w + (oc*3+ci)*4;
        acc += xp[0]*wp[0] + xp[1]*wp[1] + xp[8]*wp[2] + xp[9]*wp[3];
    }
    g_h1[idx] = gelu_f(acc);
}

// ---------------- im2col from g_h1 [b,64,49] -> g_col [256][18432] ----------------
__global__ void __launch_bounds__(256) k_im2col_a(){
    int k = blockIdx.y;
    int n = blockIdx.x*256 + threadIdx.x;
    if (n >= 18432) return;
    int ic = k>>2, tap = k&3, dy = tap>>1, dx = tap&1;
    int b = n/36, p = n - b*36;
    int py = p/6, px = p - py*6;
    g_col[(size_t)k*18432 + n] = g_h1[((size_t)b*64+ic)*49 + (py+dy)*7 + (px+dx)];
}

// ---------------- im2col from sel buffer [CIN][NB*IPIX] -> g_col [K][Ntot] ----------------
__global__ void __launch_bounds__(256) k_im2col_b(int selSrc, int IPIX, int IW,
                                                  int OW, int OPIX, int Ntot){
    const float* src = g_selbuf(selSrc);
    int k = blockIdx.y;
    int n = blockIdx.x*256 + threadIdx.x;
    if (n >= Ntot) return;
    int ic = k>>2, tap = k&3, dy = tap>>1, dx = tap&1;
    int b = n/OPIX, p = n - b*OPIX;
    int py = p/OW, px = p - py*OW;
    g_col[(size_t)k*Ntot + n] = src[(size_t)ic*(NB*IPIX) + b*IPIX + (py+dy)*IW + (px+dx)];
}

// ---------------- 128x128x16 SGEMM: C[M,N] = act(A[M,K] @ B[K,N] + bias) ----------------
// 256 threads, 8x8 microtile, register prefetch of next K-tile.
// N must be a multiple of 128; K a multiple of 16; M guarded.
template<int GELU, int HEAD, int BIASM>
__global__ void __launch_bounds__(256) k_bgemm(const float* __restrict__ Aext,
                                               const float* __restrict__ Bext,
                                               const float* __restrict__ bias,
                                               float* __restrict__ Cext,
                                               int M, int K, int N,
                                               int selA, int selB, int selC){
    const float* A = (selA < 0) ? Aext : (const float*)g_selbuf(selA);
    const float* B = (selB < 0) ? Bext : (const float*)g_selbuf(selB);
    float*       C = (selC < 0) ? Cext : g_selbuf(selC);
    __shared__ float As[16][128];
    __shared__ float Bs[16][128];
    int tid = threadIdx.x;
    int n0 = blockIdx.x*128, m0 = blockIdx.y*128;
    int tx = tid&15, ty = tid>>4;            // 16 x 16 -> 8x8 each
    // A tile loads: 128x16 = 512 float4, 2/thread: rows f>>2, cols (f&3)*4
    int aR0 = tid>>2,        aC0 = (tid&3)*4;
    int aR1 = (tid+256)>>2,  aC1 = aC0;      // same col group
    // B tile loads: 16x128 = 512 float4, 2/thread
    int bK0 = tid>>5,        bC0 = (tid&31)*4;
    int bK1 = (tid+256)>>5,  bC1 = bC0;

    float4 pa0, pa1, pb0, pb1;
    {
        int r0 = m0 + aR0, r1 = m0 + aR1;
        pa0 = (r0 < M) ? *(const float4*)&A[(size_t)r0*K + aC0] : make_float4(0.f,0.f,0.f,0.f);
        pa1 = (r1 < M) ? *(const float4*)&A[(size_t)r1*K + aC1] : make_float4(0.f,0.f,0.f,0.f);
        pb0 = *(const float4*)&B[(size_t)bK0*N + n0 + bC0];
        pb1 = *(const float4*)&B[(size_t)bK1*N + n0 + bC1];
    }

    float acc[8][8];
    #pragma unroll
    for (int u=0;u<8;u++)
        #pragma unroll
        for (int v=0;v<8;v++) acc[u][v]=0.f;

    for (int k0=0; k0<K; k0+=16){
        // store prefetched tile to smem
        As[aC0+0][aR0]=pa0.x; As[aC0+1][aR0]=pa0.y; As[aC0+2][aR0]=pa0.z; As[aC0+3][aR0]=pa0.w;
        As[aC1+0][aR1]=pa1.x; As[aC1+1][aR1]=pa1.y; As[aC1+2][aR1]=pa1.z; As[aC1+3][aR1]=pa1.w;
        *(float4*)&Bs[bK0][bC0] = pb0;
        *(float4*)&Bs[bK1][bC1] = pb1;
        __syncthreads();
        // prefetch next tile
        int kn = k0 + 16;
        if (kn < K){
            int r0 = m0 + aR0, r1 = m0 + aR1;
            pa0 = (r0 < M) ? *(const float4*)&A[(size_t)r0*K + kn + aC0] : make_float4(0.f,0.f,0.f,0.f);
            pa1 = (r1 < M) ? *(const float4*)&A[(size_t)r1*K + kn + aC1] : make_float4(0.f,0.f,0.f,0.f);
            pb0 = *(const float4*)&B[(size_t)(kn+bK0)*N + n0 + bC0];
            pb1 = *(const float4*)&B[(size_t)(kn+bK1)*N + n0 + bC1];
        }
        // compute
        #pragma unroll
        for (int kk=0; kk<16; kk++){
            float4 a40 = *(const float4*)&As[kk][ty*8];
            float4 a41 = *(const float4*)&As[kk][ty*8+4];
            float4 b40 = *(const float4*)&Bs[kk][tx*8];
            float4 b41 = *(const float4*)&Bs[kk][tx*8+4];
            float a_[8] = {a40.x,a40.y,a40.z,a40.w, a41.x,a41.y,a41.z,a41.w};
            float b_[8] = {b40.x,b40.y,b40.z,b40.w, b41.x,b41.y,b41.z,b41.w};
            #pragma unroll
            for (int u=0;u<8;u++)
                #pragma unroll
                for (int v=0;v<8;v++) acc[u][v] = fmaf(a_[u], b_[v], acc[u][v]);
        }
        __syncthreads();
    }
    #pragma unroll
    for (int u=0;u<8;u++){
        int m = m0 + ty*8 + u;
        if (m >= M) continue;
        float bm = BIASM ? bias[m] : 0.f;
        #pragma unroll
        for (int v=0;v<8;v++){
            int c = n0 + tx*8 + v;
            float val = acc[u][v] + (BIASM ? bm : bias[c]);
            if (GELU) val = gelu_f(val);
            if (HEAD) C[(m>>2)*512 + c*4 + (m&3)] = val;
            else      C[(size_t)m*N + c] = val;
        }
    }
}

// ---------------- squash g_cp [96][512*16] -> g_u [b,96,16] ----------------
__global__ void __launch_bounds__(256) k_squash(){
    int e = blockIdx.x*256 + threadIdx.x;
    if (e >= NI*NB) return;
    int oc = e>>9, b = e&511;
    const float* src = &g_cp[(size_t)oc*8192 + b*16];
    float v[16];
    float nn = 0.f;
    #pragma unroll
    for (int p=0;p<16;p++){ v[p]=src[p]; nn += v[p]*v[p]; }
    float n = __fsqrt_rn(nn);
    float sc = (1.f - exp_inline(-n)) * __frcp_rn(n + 1e-8f);
    float* dst = &g_u[((size_t)b*NI+oc)*ND];
    #pragma unroll
    for (int p=0;p<16;p++) dst[p] = v[p]*sc;
}

// ---------------- einsum: u_hat[b,o,i,d] = sum_k W[o,i,d,k] u[b,i,k] (fp16 out) ----------------
__global__ void __launch_bounds__(384) k_einsum(const float* __restrict__ W){
    extern __shared__ float ush[];
    int b0 = blockIdx.x * 16;
    int o  = blockIdx.y;
    int tid = threadIdx.x;
    for (int e=tid; e<16*NI*ND; e+=384){
        int bb = e/1536; int r = e - bb*1536; int i = r>>4; int k = r&15;
        ush[(bb*NI+i)*20 + k] = g_u[(b0+bb)*1536 + r];
    }
    __syncthreads();
    int i = tid>>2, dq = tid&3;
    const float4* Wv = (const float4*)(W + ((size_t)(o*NI + i)*ND + dq*4)*ND);
    float4 wr[16];
    #pragma unroll
    for (int t=0;t<16;t++) wr[t]=Wv[t];
    #pragma unroll 4
    for (int bb=0; bb<16; bb++){
        const float* ub = &ush[(bb*NI+i)*20];
        float4 u0=*(const float4*)(ub), u1=*(const float4*)(ub+4),
               u2=*(const float4*)(ub+8), u3=*(const float4*)(ub+12);
        float a0, a1, a2, a3;
        {
            float4 wa=wr[0], wb=wr[1], wc=wr[2], wd=wr[3];
            a0 = wa.x*u0.x + wa.y*u0.y + wa.z*u0.z + wa.w*u0.w
               + wb.x*u1.x + wb.y*u1.y + wb.z*u1.z + wb.w*u1.w
               + wc.x*u2.x + wc.y*u2.y + wc.z*u2.z + wc.w*u2.w
               + wd.x*u3.x + wd.y*u3.y + wd.z*u3.z + wd.w*u3.w;
        }
        {
            float4 wa=wr[4], wb=wr[5], wc=wr[6], wd=wr[7];
            a1 = wa.x*u0.x + wa.y*u0.y + wa.z*u0.z + wa.w*u0.w
               + wb.x*u1.x + wb.y*u1.y + wb.z*u1.z + wb.w*u1.w
               + wc.x*u2.x + wc.y*u2.y + wc.z*u2.z + wc.w*u2.w
               + wd.x*u3.x + wd.y*u3.y + wd.z*u3.z + wd.w*u3.w;
        }
        {
            float4 wa=wr[8], wb=wr[9], wc=wr[10], wd=wr[11];
            a2 = wa.x*u0.x + wa.y*u0.y + wa.z*u0.z + wa.w*u0.w
               + wb.x*u1.x + wb.y*u1.y + wb.z*u1.z + wb.w*u1.w
               + wc.x*u2.x + wc.y*u2.y + wc.z*u2.z + wc.w*u2.w
               + wd.x*u3.x + wd.y*u3.y + wd.z*u3.z + wd.w*u3.w;
        }
        {
            float4 wa=wr[12], wb=wr[13], wc=wr[14], wd=wr[15];
            a3 = wa.x*u0.x + wa.y*u0.y + wa.z*u0.z + wa.w*u0.w
               + wb.x*u1.x + wb.y*u1.y + wb.z*u1.z + wb.w*u1.w
               + wc.x*u2.x + wc.y*u2.y + wc.z*u2.z + wc.w*u2.w
               + wd.x*u3.x + wd.y*u3.y + wd.z*u3.z + wd.w*u3.w;
        }
        __half2 p0 = __floats2half2_rn(a0, a1);
        __half2 p1 = __floats2half2_rn(a2, a3);
        size_t base = (((size_t)(b0+bb)*NO + o)*NI + i)*ND + dq*4;
        *(__half2*)&g_uhat[base]     = p0;
        *(__half2*)&g_uhat[base + 2] = p1;
    }
}

// ---------------- fused routing: 3 iterations + softmax + peaks; one block per b ----------------
__global__ void __launch_bounds__(512) k_routefuse(const float* __restrict__ caps_b,
                                                   float* __restrict__ d_out){
    extern __shared__ float sm[];
    float* bm  = sm;
    float* mx  = sm + 17376;
    float* inv = sm + 17472;
    float* red = sm + 17568;
    float* len = sm + 17952;
    float* pk  = sm + 18144;
    __shared__ float s_sum;
    int b = blockIdx.x;
    int t = threadIdx.x;
    for (int e=t; e<BOI; e+=512) bm[e] = caps_b[e];
    if (t < 192) len[t] = 0.f;
    __syncthreads();
    int wid = t>>5, lane = t&31;
    int i0 = lane*3;
    for (int iter=0; iter<3; iter++){
        if (t < 384){
            int i = t % 96, g = t / 96;
            float m = -1e30f;
            for (int o=g; o<NO; o+=4) m = fmaxf(m, bm[o*96+i]);
            red[g*96+i] = m;
        }
        __syncthreads();
        if (t < 96) mx[t] = fmaxf(fmaxf(red[t], red[96+t]), fmaxf(red[192+t], red[288+t]));
        __syncthreads();
        if (t < 384){
            int i = t % 96, g = t / 96;
            float m = mx[i];
            float s = 0.f;
            for (int o=g; o<NO; o+=4) s += __expf(bm[o*96+i] - m);
            red[g*96+i] = s;
        }
        __syncthreads();
        if (t < 96) inv[t] = __frcp_rn(red[t]+red[96+t]+red[192+t]+red[288+t]);
        __syncthreads();
        int last = (iter==2);
        for (int o=wid; o<NO; o+=16){
            const float4* hp = (const float4*)(g_uhat + ((size_t)b*NO + o)*1536 + lane*48);
            float hf[48];
            #pragma unroll
            for (int q=0;q<6;q++){
                float4 r4 = hp[q];
                const __half2* hh = (const __half2*)&r4;
                #pragma unroll
                for (int x=0;x<4;x++){
                    float2 f = __half22float2(hh[x]);
                    hf[q*8+x*2]   = f.x;
                    hf[q*8+x*2+1] = f.y;
                }
            }
            float c0 = __expf(bm[o*96+i0  ] - mx[i0  ]) * inv[i0  ];
            float c1 = __expf(bm[o*96+i0+1] - mx[i0+1]) * inv[i0+1];
            float c2 = __expf(bm[o*96+i0+2] - mx[i0+2]) * inv[i0+2];
            float S[16];
            #pragma unroll
            for (int d=0;d<16;d++)
                S[d] = c0*hf[d] + c1*hf[16+d] + c2*hf[32+d];
            #pragma unroll
            for (int off=16; off>0; off>>=1){
                #pragma unroll
                for (int d=0;d<16;d++) S[d] += __shfl_xor_sync(0xffffffffu, S[d], off);
            }
            float nn = 0.f;
            #pragma unroll
            for (int d=0;d<16;d++) nn += S[d]*S[d];
            float n = __fsqrt_rn(nn);
            float sc = (1.f - __expf(-n)) * __frcp_rn(n + 1e-8f);
            if (!last){
                float d0=0.f, d1=0.f, d2=0.f;
                #pragma unroll
                for (int d=0;d<16;d++){
                    float vd = S[d]*sc;
                    d0 = fmaf(vd, hf[d],    d0);
                    d1 = fmaf(vd, hf[16+d], d1);
                    d2 = fmaf(vd, hf[32+d], d2);
                }
                bm[o*96+i0  ] += d0;
                bm[o*96+i0+1] += d1;
                bm[o*96+i0+2] += d2;
            } else {
                if (lane < 16) g_x[((size_t)b*NO+o)*ND + lane] = S[lane]*sc;
                if (lane == 0) len[o] = n*sc;
            }
        }
        __syncthreads();
    }
    if (t==0){
        float s=0.f;
        for (int o=0;o<NO;o++) s+=len[o];
        s_sum = s + 1e-8f;
    }
    __syncthreads();
    if (t < NO) len[t] = len[t] / s_sum;
    __syncthreads();
    if (t < NO){
        float m = -1e30f;
        #pragma unroll
        for (int dd=-5; dd<=5; dd++){
            int oo = t+dd;
            if (oo>=0 && oo<NO) m = fmaxf(m, len[oo]);
        }
        pk[t] = (len[t]==m) ? len[t] : 0.f;
        d_out[NB*128*4 + b*NO + t] = len[t];
    } else if (t < 192) pk[t] = 0.f;
    __syncthreads();
    if (t==0){
        int i0s, i1s, i2s, i3s;
        {
            float bv=-1.f; int bi=0;
            for (int o=0;o<NO;o++){ float v=pk[o]; if (v>bv){ bv=v; bi=o; } }
            i0s=bi; pk[bi]=-2.f;
        }
        {
            float bv=-1.f; int bi=0;
            for (int o=0;o<NO;o++){ float v=pk[o]; if (v>bv){ bv=v; bi=o; } }
            i1s=bi; pk[bi]=-2.f;
        }
        {
            float bv=-1.f; int bi=0;
            for (int o=0;o<NO;o++){ float v=pk[o]; if (v>bv){ bv=v; bi=o; } }
            i2s=bi; pk[bi]=-2.f;
        }
        {
            float bv=-1.f; int bi=0;
            for (int o=0;o<NO;o++){ float v=pk[o]; if (v>bv){ bv=v; bi=o; } }
            i3s=bi;
        }
        int tmp;
        if (i0s>i1s){tmp=i0s;i0s=i1s;i1s=tmp;}
        if (i2s>i3s){tmp=i2s;i2s=i3s;i3s=tmp;}
        if (i0s>i2s){tmp=i0s;i0s=i2s;i2s=tmp;}
        if (i1s>i3s){tmp=i1s;i1s=i3s;i3s=tmp;}
        if (i1s>i2s){tmp=i1s;i1s=i2s;i2s=tmp;}
        g_idx[b*4+0]=i0s; g_idx[b*4+1]=i1s; g_idx[b*4+2]=i2s; g_idx[b*4+3]=i3s;
    }
}

// ---------------- fc1 (sparse gather GEMV) -> gelu -> g_a1 [2048,1024] ----------------
__global__ void __launch_bounds__(256) k_fc1(const float* __restrict__ w,
                                             const float* __restrict__ bias){
    int j = blockIdx.x*256 + threadIdx.x;
    int row = blockIdx.y;
    if (j >= 1024) return;
    int b = row>>2, k = row&3;
    int id = g_idx[b*4+k];
    const float* xv = &g_x[(b*NO+id)*ND];
    float acc = bias[j];
    #pragma unroll
    for (int d=0; d<16; d++) acc += xv[d]*w[(id*16+d)*1024 + j];
    g_a1[row*1024 + j] = gelu_f(acc);
}

// ---------------- launch ----------------
extern "C" void kernel_launch(void* const* d_in, const int* in_sizes, int n_in,
                              void* d_out, int out_size){
    const float* scm     = (const float*)d_in[0];
    const float* w1 = (const float*)d_in[2];  const float* b1 = (const float*)d_in[3];
    const float* w2 = (const float*)d_in[4];  const float* b2 = (const float*)d_in[5];
    const float* w3 = (const float*)d_in[6];  const float* b3 = (const float*)d_in[7];
    const float* pw = (const float*)d_in[8];  const float* pb = (const float*)d_in[9];
    const float* capsW = (const float*)d_in[10];
    const float* capsB = (const float*)d_in[11];
    const float* f1w = (const float*)d_in[12]; const float* f1b = (const float*)d_in[13];
    const float* f2w = (const float*)d_in[14]; const float* f2b = (const float*)d_in[15];
    const float* f3w = (const float*)d_in[16]; const float* f3b = (const float*)d_in[17];
    const float* f4w = (const float*)d_in[18]; const float* f4b = (const float*)d_in[19];
    const float* f5w = (const float*)d_in[20]; const float* f5b = (const float*)d_in[21];
    const float* hw  = (const float*)d_in[22]; const float* hb  = (const float*)d_in[23];
    float* out = (float*)d_out;

    const int einsum_smem = 16*NI*20*4;   // 122880 B
    const int route_smem  = 120*1024;     // pad to force 1 block/SM (L2 residency)
    cudaFuncSetAttribute(k_einsum,    cudaFuncAttributeMaxDynamicSharedMemorySize, einsum_smem);
    cudaFuncSetAttribute(k_routefuse, cudaFuncAttributeMaxDynamicSharedMemorySize, route_smem);

    // conv stack as im2col + GEMM (N multiples of 128)
    k_conv1<<<(NB*64*49 + 255)/256, 256>>>(scm, w1, b1);
    k_im2col_a<<<dim3(72, 256), 256>>>();
    k_bgemm<1,0,1><<<dim3(144, 1), 256>>>(w2, nullptr, b2, nullptr, 128, 256, 18432, -1, 0, 1);
    k_im2col_b<<<dim3(50, 512), 256>>>(1, 36, 6, 5, 25, 12800);
    k_bgemm<1,0,1><<<dim3(100, 2), 256>>>(w3, nullptr, b3, nullptr, 256, 512, 12800, -1, 0, 2);
    k_im2col_b<<<dim3(32, 1024), 256>>>(2, 25, 5, 4, 16, 8192);
    k_bgemm<0,0,1><<<dim3(64, 1), 256>>>(pw, nullptr, pb, nullptr, 96, 1024, 8192, -1, 0, 3);
    k_squash<<<(NI*NB + 255)/256, 256>>>();

    // capsule layer
    k_einsum<<<dim3(32, NO), 384, einsum_smem>>>(capsW);
    k_routefuse<<<NB, 512, route_smem>>>(capsB, out);

    // MLP tail
    k_fc1<<<dim3(4, 2048), 256>>>(f1w, f1b);
    k_bgemm<1,0,0><<<dim3(6, 16), 256>>>(nullptr, f2w, f2b, nullptr, 2048, 1024, 768, 4, -1, 5);
    k_bgemm<1,0,0><<<dim3(4, 16), 256>>>(nullptr, f3w, f3b, nullptr, 2048, 768,  512, 5, -1, 6);
    k_bgemm<1,0,0><<<dim3(4, 16), 256>>>(nullptr, f4w, f4b, nullptr, 2048, 512,  512, 6, -1, 7);
    k_bgemm<1,0,0><<<dim3(2, 16), 256>>>(nullptr, f5w, f5b, nullptr, 2048, 512,  256, 7, -1, 8);
    k_bgemm<0,1,0><<<dim3(1, 16), 256>>>(nullptr, hw,  hb,  out,     2048, 256,  128, 8, -1, -1);
    (void)in_sizes; (void)n_in; (void)out_size;
}

// round 9
// speedup vs baseline: 1.1441x; 1.1441x over previous
#include <cuda_runtime.h>
#include <cuda_fp16.h>

#define DEV_INLINE __device__ __forceinline__

// fully-inline erf (Abramowitz-Stegun 7.1.26, |err| <= 1.5e-7) -> exact-gelu
static DEV_INLINE float erf_inline(float x){
    float ax = fabsf(x);
    float t = __frcp_rn(fmaf(0.3275911f, ax, 1.0f));
    float y = fmaf(t, 1.061405429f, -1.453152027f);
    y = fmaf(t, y, 1.421413741f);
    y = fmaf(t, y, -0.284496736f);
    y = fmaf(t, y, 0.254829592f);
    y = y * t;
    float e = __expf(-ax*ax);
    float r = fmaf(-y, e, 1.0f);
    return copysignf(r, x);
}
static DEV_INLINE float gelu_f(float x){
    return 0.5f * x * (1.f + erf_inline(x * 0.70710678118654752440f));
}
static DEV_INLINE float exp_inline(float x){ return __expf(x); }

#define NB 512
#define NO 181
#define NI 96
#define ND 16
#define BOI (NO*NI)   // 17376

// ---------------- scratch (device globals; referenced ONLY from device code) ----------------
__device__ float  g_h1[NB*64*49];                 // conv1 out [b,ic,49]
__device__ float  g_col[1024*8192];               // im2col buffer
__device__ float  g_c2 [128*18432];               // conv2 out [oc, b*36+p]
__device__ float  g_c3 [256*12800];               // conv3 out [oc, b*25+p]
__device__ float  g_cp [96*8192];                 // pc conv out [oc, b*16+p]
__device__ float  g_u  [NB*NI*ND];
__device__ __half g_uhat[(size_t)NB*NO*NI*ND];    // 285 MB (fp16)
__device__ float  g_x  [NB*NO*ND];
__device__ int    g_idx[NB*4];
__device__ float  g_a1[2048*1024];
__device__ float  g_a2[2048*768];
__device__ float  g_a3[2048*512];
__device__ float  g_a4[2048*512];
__device__ float  g_a5[2048*256];

__device__ DEV_INLINE float* g_selbuf(int s){
    switch(s){
        case 0: return g_col;
        case 1: return g_c2;
        case 2: return g_c3;
        case 3: return g_cp;
        case 4: return g_a1;
        case 5: return g_a2;
        case 6: return g_a3;
        case 7: return g_a4;
        case 8: return g_a5;
    }
    return nullptr;
}

// ---------------- conv1: [512,3,8,8] -> gelu -> [512,64,7,7] ----------------
__global__ void __launch_bounds__(256) k_conv1(const float* __restrict__ x,
                                               const float* __restrict__ w,
                                               const float* __restrict__ bias){
    int idx = blockIdx.x*256 + threadIdx.x;
    if (idx >= NB*64*49) return;
    int p = idx % 49; int oc = (idx/49) & 63; int b = idx/(49*64);
    int y = p/7, xx = p%7;
    float acc = bias[oc];
    #pragma unroll
    for (int ci=0; ci<3; ci++){
        const float* xp = x + (b*3+ci)*64 + y*8 + xx;
        const float* wp = w + (oc*3+ci)*4;
        acc += xp[0]*wp[0] + xp[1]*wp[1] + xp[8]*wp[2] + xp[9]*wp[3];
    }
    g_h1[idx] = gelu_f(acc);
}

// ---------------- im2col from g_h1 [b,64,49] -> g_col [256][18432] ----------------
__global__ void __launch_bounds__(256) k_im2col_a(){
    int k = blockIdx.y;
    int n = blockIdx.x*256 + threadIdx.x;
    if (n >= 18432) return;
    int ic = k>>2, tap = k&3, dy = tap>>1, dx = tap&1;
    int b = n/36, p = n - b*36;
    int py = p/6, px = p - py*6;
    g_col[(size_t)k*18432 + n] = g_h1[((size_t)b*64+ic)*49 + (py+dy)*7 + (px+dx)];
}

// ---------------- im2col from sel buffer [CIN][NB*IPIX] -> g_col [K][Ntot] ----------------
__global__ void __launch_bounds__(256) k_im2col_b(int selSrc, int IPIX, int IW,
                                                  int OW, int OPIX, int Ntot){
    const float* src = g_selbuf(selSrc);
    int k = blockIdx.y;
    int n = blockIdx.x*256 + threadIdx.x;
    if (n >= Ntot) return;
    int ic = k>>2, tap = k&3, dy = tap>>1, dx = tap&1;
    int b = n/OPIX, p = n - b*OPIX;
    int py = p/OW, px = p - py*OW;
    g_col[(size_t)k*Ntot + n] = src[(size_t)ic*(NB*IPIX) + b*IPIX + (py+dy)*IW + (px+dx)];
}

// ---------------- 128x128x16 SGEMM: C[M,N] = act(A[M,K] @ B[K,N] + bias) ----------------
template<int GELU, int HEAD, int BIASM>
__global__ void __launch_bounds__(256) k_bgemm(const float* __restrict__ Aext,
                                               const float* __restrict__ Bext,
                                               const float* __restrict__ bias,
                                               float* __restrict__ Cext,
                                               int M, int K, int N,
                                               int selA, int selB, int selC){
    const float* A = (selA < 0) ? Aext : (const float*)g_selbuf(selA);
    const float* B = (selB < 0) ? Bext : (const float*)g_selbuf(selB);
    float*       C = (selC < 0) ? Cext : g_selbuf(selC);
    __shared__ float As[16][128];
    __shared__ float Bs[16][128];
    int tid = threadIdx.x;
    int n0 = blockIdx.x*128, m0 = blockIdx.y*128;
    int tx = tid&15, ty = tid>>4;
    int aR0 = tid>>2,        aC0 = (tid&3)*4;
    int aR1 = (tid+256)>>2,  aC1 = aC0;
    int bK0 = tid>>5,        bC0 = (tid&31)*4;
    int bK1 = (tid+256)>>5,  bC1 = bC0;

    float4 pa0, pa1, pb0, pb1;
    {
        int r0 = m0 + aR0, r1 = m0 + aR1;
        pa0 = (r0 < M) ? *(const float4*)&A[(size_t)r0*K + aC0] : make_float4(0.f,0.f,0.f,0.f);
        pa1 = (r1 < M) ? *(const float4*)&A[(size_t)r1*K + aC1] : make_float4(0.f,0.f,0.f,0.f);
        pb0 = *(const float4*)&B[(size_t)bK0*N + n0 + bC0];
        pb1 = *(const float4*)&B[(size_t)bK1*N + n0 + bC1];
    }

    float acc[8][8];
    #pragma unroll
    for (int u=0;u<8;u++)
        #pragma unroll
        for (int v=0;v<8;v++) acc[u][v]=0.f;

    for (int k0=0; k0<K; k0+=16){
        As[aC0+0][aR0]=pa0.x; As[aC0+1][aR0]=pa0.y; As[aC0+2][aR0]=pa0.z; As[aC0+3][aR0]=pa0.w;
        As[aC1+0][aR1]=pa1.x; As[aC1+1][aR1]=pa1.y; As[aC1+2][aR1]=pa1.z; As[aC1+3][aR1]=pa1.w;
        *(float4*)&Bs[bK0][bC0] = pb0;
        *(float4*)&Bs[bK1][bC1] = pb1;
        __syncthreads();
        int kn = k0 + 16;
        if (kn < K){
            int r0 = m0 + aR0, r1 = m0 + aR1;
            pa0 = (r0 < M) ? *(const float4*)&A[(size_t)r0*K + kn + aC0] : make_float4(0.f,0.f,0.f,0.f);
            pa1 = (r1 < M) ? *(const float4*)&A[(size_t)r1*K + kn + aC1] : make_float4(0.f,0.f,0.f,0.f);
            pb0 = *(const float4*)&B[(size_t)(kn+bK0)*N + n0 + bC0];
            pb1 = *(const float4*)&B[(size_t)(kn+bK1)*N + n0 + bC1];
        }
        #pragma unroll
        for (int kk=0; kk<16; kk++){
            float4 a40 = *(const float4*)&As[kk][ty*8];
            float4 a41 = *(const float4*)&As[kk][ty*8+4];
            float4 b40 = *(const float4*)&Bs[kk][tx*8];
            float4 b41 = *(const float4*)&Bs[kk][tx*8+4];
            float a_[8] = {a40.x,a40.y,a40.z,a40.w, a41.x,a41.y,a41.z,a41.w};
            float b_[8] = {b40.x,b40.y,b40.z,b40.w, b41.x,b41.y,b41.z,b41.w};
            #pragma unroll
            for (int u=0;u<8;u++)
                #pragma unroll
                for (int v=0;v<8;v++) acc[u][v] = fmaf(a_[u], b_[v], acc[u][v]);
        }
        __syncthreads();
    }
    #pragma unroll
    for (int u=0;u<8;u++){
        int m = m0 + ty*8 + u;
        if (m >= M) continue;
        float bm = BIASM ? bias[m] : 0.f;
        #pragma unroll
        for (int v=0;v<8;v++){
            int c = n0 + tx*8 + v;
            float val = acc[u][v] + (BIASM ? bm : bias[c]);
            if (GELU) val = gelu_f(val);
            if (HEAD) C[(m>>2)*512 + c*4 + (m&3)] = val;
            else      C[(size_t)m*N + c] = val;
        }
    }
}

// ---------------- squash g_cp [96][512*16] -> g_u [b,96,16] ----------------
__global__ void __launch_bounds__(256) k_squash(){
    int e = blockIdx.x*256 + threadIdx.x;
    if (e >= NI*NB) return;
    int oc = e>>9, b = e&511;
    const float* src = &g_cp[(size_t)oc*8192 + b*16];
    float v[16];
    float nn = 0.f;
    #pragma unroll
    for (int p=0;p<16;p++){ v[p]=src[p]; nn += v[p]*v[p]; }
    float n = __fsqrt_rn(nn);
    float sc = (1.f - exp_inline(-n)) * __frcp_rn(n + 1e-8f);
    float* dst = &g_u[((size_t)b*NI+oc)*ND];
    #pragma unroll
    for (int p=0;p<16;p++) dst[p] = v[p]*sc;
}

// ---------------- einsum v2: persistent block per (half-batch, o) ----------------
// grid (2, 181), 384 thr = (i 0..95) x (dq 0..3). W[o] lives in registers for the
// whole block; u streamed through a double-buffered 4-batch smem chunk.
// smem: 2 x [4][96][20] floats = 61440 B -> 3 blocks/SM, 362 blocks ~= 0.8 waves.
__global__ void __launch_bounds__(384) k_einsum(const float* __restrict__ W){
    extern __shared__ float ush[];            // [2][4*96*20]
    const int BUF = 4*96*20;                  // 7680 floats
    int half = blockIdx.x;                    // 0..1 -> batches half*256 .. +255
    int o    = blockIdx.y;
    int tid  = threadIdx.x;
    int i = tid>>2, dq = tid&3;

    // W[o][i][dq*4 + d4][k] into regs
    const float4* Wv = (const float4*)(W + ((size_t)(o*NI + i)*ND + dq*4)*ND);
    float4 wr[16];
    #pragma unroll
    for (int t=0;t<16;t++) wr[t]=Wv[t];

    int b_base = half*256;
    const float4* usrc = (const float4*)(g_u + (size_t)b_base*1536);
    // chunk = 4 batches = 1536 float4; thread loads float4 'tid' of each batch j
    int si = tid>>2, sk4 = (tid&3)*4;         // smem dest decomposition of tid

    // preload chunk 0
    float4 pre[4];
    #pragma unroll
    for (int j=0;j<4;j++) pre[j] = usrc[j*384 + tid];
    {
        float* b0 = ush;
        #pragma unroll
        for (int j=0;j<4;j++) *(float4*)&b0[(j*96+si)*20 + sk4] = pre[j];
    }
    __syncthreads();

    for (int c=0; c<64; c++){
        const float* cur = ush + (c&1)*BUF;
        float*       nxt = ush + ((c+1)&1)*BUF;
        if (c < 63){
            const float4* s2 = usrc + (size_t)(c+1)*1536;
            #pragma unroll
            for (int j=0;j<4;j++) pre[j] = s2[j*384 + tid];
        }
        #pragma unroll
        for (int bb=0; bb<4; bb++){
            const float* ub = &cur[(bb*96+i)*20];
            float4 u0=*(const float4*)(ub), u1=*(const float4*)(ub+4),
                   u2=*(const float4*)(ub+8), u3=*(const float4*)(ub+12);
            float a0, a1, a2, a3;
            {
                float4 wa=wr[0], wb=wr[1], wc=wr[2], wd=wr[3];
                a0 = wa.x*u0.x + wa.y*u0.y + wa.z*u0.z + wa.w*u0.w
                   + wb.x*u1.x + wb.y*u1.y + wb.z*u1.z + wb.w*u1.w
                   + wc.x*u2.x + wc.y*u2.y + wc.z*u2.z + wc.w*u2.w
                   + wd.x*u3.x + wd.y*u3.y + wd.z*u3.z + wd.w*u3.w;
            }
            {
                float4 wa=wr[4], wb=wr[5], wc=wr[6], wd=wr[7];
                a1 = wa.x*u0.x + wa.y*u0.y + wa.z*u0.z + wa.w*u0.w
                   + wb.x*u1.x + wb.y*u1.y + wb.z*u1.z + wb.w*u1.w
                   + wc.x*u2.x + wc.y*u2.y + wc.z*u2.z + wc.w*u2.w
                   + wd.x*u3.x + wd.y*u3.y + wd.z*u3.z + wd.w*u3.w;
            }
            {
                float4 wa=wr[8], wb=wr[9], wc=wr[10], wd=wr[11];
                a2 = wa.x*u0.x + wa.y*u0.y + wa.z*u0.z + wa.w*u0.w
                   + wb.x*u1.x + wb.y*u1.y + wb.z*u1.z + wb.w*u1.w
                   + wc.x*u2.x + wc.y*u2.y + wc.z*u2.z + wc.w*u2.w
                   + wd.x*u3.x + wd.y*u3.y + wd.z*u3.z + wd.w*u3.w;
            }
            {
                float4 wa=wr[12], wb=wr[13], wc=wr[14], wd=wr[15];
                a3 = wa.x*u0.x + wa.y*u0.y + wa.z*u0.z + wa.w*u0.w
                   + wb.x*u1.x + wb.y*u1.y + wb.z*u1.z + wb.w*u1.w
                   + wc.x*u2.x + wc.y*u2.y + wc.z*u2.z + wc.w*u2.w
                   + wd.x*u3.x + wd.y*u3.y + wd.z*u3.z + wd.w*u3.w;
            }
            __half2 p0 = __floats2half2_rn(a0, a1);
            __half2 p1 = __floats2half2_rn(a2, a3);
            int b = b_base + c*4 + bb;
            size_t base = (((size_t)b*NO + o)*NI + i)*ND + dq*4;
            *(__half2*)&g_uhat[base]     = p0;
            *(__half2*)&g_uhat[base + 2] = p1;
        }
        if (c < 63){
            #pragma unroll
            for (int j=0;j<4;j++) *(float4*)&nxt[(j*96+si)*20 + sk4] = pre[j];
        }
        __syncthreads();
    }
}

// ---------------- fused routing: 3 iterations + softmax + peaks; one block per b ----------------
__global__ void __launch_bounds__(512) k_routefuse(const float* __restrict__ caps_b,
                                                   float* __restrict__ d_out){
    extern __shared__ float sm[];
    float* bm  = sm;
    float* mx  = sm + 17376;
    float* inv = sm + 17472;
    float* red = sm + 17568;
    float* len = sm + 17952;
    float* pk  = sm + 18144;
    __shared__ float s_sum;
    int b = blockIdx.x;
    int t = threadIdx.x;
    for (int e=t; e<BOI; e+=512) bm[e] = caps_b[e];
    if (t < 192) len[t] = 0.f;
    __syncthreads();
    int wid = t>>5, lane = t&31;
    int i0 = lane*3;
    for (int iter=0; iter<3; iter++){
        if (t < 384){
            int i = t % 96, g = t / 96;
            float m = -1e30f;
            for (int o=g; o<NO; o+=4) m = fmaxf(m, bm[o*96+i]);
            red[g*96+i] = m;
        }
        __syncthreads();
        if (t < 96) mx[t] = fmaxf(fmaxf(red[t], red[96+t]), fmaxf(red[192+t], red[288+t]));
        __syncthreads();
        if (t < 384){
            int i = t % 96, g = t / 96;
            float m = mx[i];
            float s = 0.f;
            for (int o=g; o<NO; o+=4) s += __expf(bm[o*96+i] - m);
            red[g*96+i] = s;
        }
        __syncthreads();
        if (t < 96) inv[t] = __frcp_rn(red[t]+red[96+t]+red[192+t]+red[288+t]);
        __syncthreads();
        int last = (iter==2);
        for (int o=wid; o<NO; o+=16){
            const float4* hp = (const float4*)(g_uhat + ((size_t)b*NO + o)*1536 + lane*48);
            float hf[48];
            #pragma unroll
            for (int q=0;q<6;q++){
                float4 r4 = hp[q];
                const __half2* hh = (const __half2*)&r4;
                #pragma unroll
                for (int x=0;x<4;x++){
                    float2 f = __half22float2(hh[x]);
                    hf[q*8+x*2]   = f.x;
                    hf[q*8+x*2+1] = f.y;
                }
            }
            float c0 = __expf(bm[o*96+i0  ] - mx[i0  ]) * inv[i0  ];
            float c1 = __expf(bm[o*96+i0+1] - mx[i0+1]) * inv[i0+1];
            float c2 = __expf(bm[o*96+i0+2] - mx[i0+2]) * inv[i0+2];
            float S[16];
            #pragma unroll
            for (int d=0;d<16;d++)
                S[d] = c0*hf[d] + c1*hf[16+d] + c2*hf[32+d];
            #pragma unroll
            for (int off=16; off>0; off>>=1){
                #pragma unroll
                for (int d=0;d<16;d++) S[d] += __shfl_xor_sync(0xffffffffu, S[d], off);
            }
            float nn = 0.f;
            #pragma unroll
            for (int d=0;d<16;d++) nn += S[d]*S[d];
            float n = __fsqrt_rn(nn);
            float sc = (1.f - __expf(-n)) * __frcp_rn(n + 1e-8f);
            if (!last){
                float d0=0.f, d1=0.f, d2=0.f;
                #pragma unroll
                for (int d=0;d<16;d++){
                    float vd = S[d]*sc;
                    d0 = fmaf(vd, hf[d],    d0);
                    d1 = fmaf(vd, hf[16+d], d1);
                    d2 = fmaf(vd, hf[32+d], d2);
                }
                bm[o*96+i0  ] += d0;
                bm[o*96+i0+1] += d1;
                bm[o*96+i0+2] += d2;
            } else {
                if (lane < 16) g_x[((size_t)b*NO+o)*ND + lane] = S[lane]*sc;
                if (lane == 0) len[o] = n*sc;
            }
        }
        __syncthreads();
    }
    if (t==0){
        float s=0.f;
        for (int o=0;o<NO;o++) s+=len[o];
        s_sum = s + 1e-8f;
    }
    __syncthreads();
    if (t < NO) len[t] = len[t] / s_sum;
    __syncthreads();
    if (t < NO){
        float m = -1e30f;
        #pragma unroll
        for (int dd=-5; dd<=5; dd++){
            int oo = t+dd;
            if (oo>=0 && oo<NO) m = fmaxf(m, len[oo]);
        }
        pk[t] = (len[t]==m) ? len[t] : 0.f;
        d_out[NB*128*4 + b*NO + t] = len[t];
    } else if (t < 192) pk[t] = 0.f;
    __syncthreads();
    if (t==0){
        int i0s, i1s, i2s, i3s;
        {
            float bv=-1.f; int bi=0;
            for (int o=0;o<NO;o++){ float v=pk[o]; if (v>bv){ bv=v; bi=o; } }
            i0s=bi; pk[bi]=-2.f;
        }
        {
            float bv=-1.f; int bi=0;
            for (int o=0;o<NO;o++){ float v=pk[o]; if (v>bv){ bv=v; bi=o; } }
            i1s=bi; pk[bi]=-2.f;
        }
        {
            float bv=-1.f; int bi=0;
            for (int o=0;o<NO;o++){ float v=pk[o]; if (v>bv){ bv=v; bi=o; } }
            i2s=bi; pk[bi]=-2.f;
        }
        {
            float bv=-1.f; int bi=0;
            for (int o=0;o<NO;o++){ float v=pk[o]; if (v>bv){ bv=v; bi=o; } }
            i3s=bi;
        }
        int tmp;
        if (i0s>i1s){tmp=i0s;i0s=i1s;i1s=tmp;}
        if (i2s>i3s){tmp=i2s;i2s=i3s;i3s=tmp;}
        if (i0s>i2s){tmp=i0s;i0s=i2s;i2s=tmp;}
        if (i1s>i3s){tmp=i1s;i1s=i3s;i3s=tmp;}
        if (i1s>i2s){tmp=i1s;i1s=i2s;i2s=tmp;}
        g_idx[b*4+0]=i0s; g_idx[b*4+1]=i1s; g_idx[b*4+2]=i2s; g_idx[b*4+3]=i3s;
    }
}

// ---------------- fc1 (sparse gather GEMV) -> gelu -> g_a1 [2048,1024] ----------------
__global__ void __launch_bounds__(256) k_fc1(const float* __restrict__ w,
                                             const float* __restrict__ bias){
    int j = blockIdx.x*256 + threadIdx.x;
    int row = blockIdx.y;
    if (j >= 1024) return;
    int b = row>>2, k = row&3;
    int id = g_idx[b*4+k];
    const float* xv = &g_x[(b*NO+id)*ND];
    float acc = bias[j];
    #pragma unroll
    for (int d=0; d<16; d++) acc += xv[d]*w[(id*16+d)*1024 + j];
    g_a1[row*1024 + j] = gelu_f(acc);
}

// ---------------- launch ----------------
extern "C" void kernel_launch(void* const* d_in, const int* in_sizes, int n_in,
                              void* d_out, int out_size){
    const float* scm     = (const float*)d_in[0];
    const float* w1 = (const float*)d_in[2];  const float* b1 = (const float*)d_in[3];
    const float* w2 = (const float*)d_in[4];  const float* b2 = (const float*)d_in[5];
    const float* w3 = (const float*)d_in[6];  const float* b3 = (const float*)d_in[7];
    const float* pw = (const float*)d_in[8];  const float* pb = (const float*)d_in[9];
    const float* capsW = (const float*)d_in[10];
    const float* capsB = (const float*)d_in[11];
    const float* f1w = (const float*)d_in[12]; const float* f1b = (const float*)d_in[13];
    const float* f2w = (const float*)d_in[14]; const float* f2b = (const float*)d_in[15];
    const float* f3w = (const float*)d_in[16]; const float* f3b = (const float*)d_in[17];
    const float* f4w = (const float*)d_in[18]; const float* f4b = (const float*)d_in[19];
    const float* f5w = (const float*)d_in[20]; const float* f5b = (const float*)d_in[21];
    const float* hw  = (const float*)d_in[22]; const float* hb  = (const float*)d_in[23];
    float* out = (float*)d_out;

    const int einsum_smem = 2*4*NI*20*4;  // 61440 B (double-buffered 4-batch chunk)
    const int route_smem  = 120*1024;     // pad to force 1 block/SM (L2 residency)
    cudaFuncSetAttribute(k_einsum,    cudaFuncAttributeMaxDynamicSharedMemorySize, einsum_smem);
    cudaFuncSetAttribute(k_routefuse, cudaFuncAttributeMaxDynamicSharedMemorySize, route_smem);

    // conv stack as im2col + GEMM (N multiples of 128)
    k_conv1<<<(NB*64*49 + 255)/256, 256>>>(scm, w1, b1);
    k_im2col_a<<<dim3(72, 256), 256>>>();
    k_bgemm<1,0,1><<<dim3(144, 1), 256>>>(w2, nullptr, b2, nullptr, 128, 256, 18432, -1, 0, 1);
    k_im2col_b<<<dim3(50, 512), 256>>>(1, 36, 6, 5, 25, 12800);
    k_bgemm<1,0,1><<<dim3(100, 2), 256>>>(w3, nullptr, b3, nullptr, 256, 512, 12800, -1, 0, 2);
    k_im2col_b<<<dim3(32, 1024), 256>>>(2, 25, 5, 4, 16, 8192);
    k_bgemm<0,0,1><<<dim3(64, 1), 256>>>(pw, nullptr, pb, nullptr, 96, 1024, 8192, -1, 0, 3);
    k_squash<<<(NI*NB + 255)/256, 256>>>();

    // capsule layer
    k_einsum<<<dim3(2, NO), 384, einsum_smem>>>(capsW);
    k_routefuse<<<NB, 512, route_smem>>>(capsB, out);

    // MLP tail
    k_fc1<<<dim3(4, 2048), 256>>>(f1w, f1b);
    k_bgemm<1,0,0><<<dim3(6, 16), 256>>>(nullptr, f2w, f2b, nullptr, 2048, 1024, 768, 4, -1, 5);
    k_bgemm<1,0,0><<<dim3(4, 16), 256>>>(nullptr, f3w, f3b, nullptr, 2048, 768,  512, 5, -1, 6);
    k_bgemm<1,0,0><<<dim3(4, 16), 256>>>(nullptr, f4w, f4b, nullptr, 2048, 512,  512, 6, -1, 7);
    k_bgemm<1,0,0><<<dim3(2, 16), 256>>>(nullptr, f5w, f5b, nullptr, 2048, 512,  256, 7, -1, 8);
    k_bgemm<0,1,0><<<dim3(1, 16), 256>>>(nullptr, hw,  hb,  out,     2048, 256,  128, 8, -1, -1);
    (void)in_sizes; (void)n_in; (void)out_size;
}

// round 12
// speedup vs baseline: 1.5143x; 1.3235x over previous
#include <cuda_runtime.h>
#include <cuda_fp16.h>
#include <cstdint>

#define DEV_INLINE __device__ __forceinline__

static DEV_INLINE float erf_inline(float x){
    float ax = fabsf(x);
    float t = __frcp_rn(fmaf(0.3275911f, ax, 1.0f));
    float y = fmaf(t, 1.061405429f, -1.453152027f);
    y = fmaf(t, y, 1.421413741f);
    y = fmaf(t, y, -0.284496736f);
    y = fmaf(t, y, 0.254829592f);
    y = y * t;
    float e = __expf(-ax*ax);
    float r = fmaf(-y, e, 1.0f);
    return copysignf(r, x);
}
static DEV_INLINE float gelu_f(float x){
    return 0.5f * x * (1.f + erf_inline(x * 0.70710678118654752440f));
}
static DEV_INLINE float exp_inline(float x){ return __expf(x); }

#define NB 512
#define NO 181
#define NI 96
#define ND 16
#define BOI (NO*NI)   // 17376

// ---------------- scratch ----------------
__device__ float  g_h1[NB*64*49];
__device__ float  g_col[1024*8192];               // im2col fp32
__device__ float  g_c2 [128*18432];
__device__ float  g_c3 [256*12800];
__device__ float  g_cp [96*8192];
__device__ float  g_u  [NB*NI*ND];
__device__ __half g_uhat[(size_t)NB*NO*NI*ND];    // 285 MB
__device__ float  g_x  [NB*NO*ND];
__device__ int    g_idx[NB*4];
__device__ __half g_wh [2*1024*1024];             // fp16 MLP weights
__device__ __half g_a1h[2048*1024];
__device__ __half g_a2h[2048*768];
__device__ __half g_a3h[2048*512];
__device__ __half g_a4h[2048*512];
__device__ __half g_a5h[2048*256];

// fp16 weight offsets
#define OFF_F2 0
#define OFF_F3 786432
#define OFF_F4 1179648
#define OFF_F5 1441792
#define OFF_HW 1572864

__device__ DEV_INLINE float* g_selbuf(int s){
    switch(s){
        case 0: return g_col;
        case 1: return g_c2;
        case 2: return g_c3;
        case 3: return g_cp;
    }
    return nullptr;
}
__device__ DEV_INLINE __half* g_selh(int s){
    switch(s){
        case 4: return g_a1h;
        case 5: return g_a2h;
        case 6: return g_a3h;
        case 7: return g_a4h;
        case 8: return g_a5h;
        case 9: return g_wh;
    }
    return nullptr;
}

// ---------------- fp32 -> fp16 weight convert ----------------
__global__ void __launch_bounds__(256) k_tohalf(const float* __restrict__ src, int off, int n){
    int i = blockIdx.x*256 + threadIdx.x;
    if (i < n) g_wh[off + i] = __float2half(src[i]);
}

// ---------------- conv1 ----------------
__global__ void __launch_bounds__(256) k_conv1(const float* __restrict__ x,
                                               const float* __restrict__ w,
                                               const float* __restrict__ bias){
    int idx = blockIdx.x*256 + threadIdx.x;
    if (idx >= NB*64*49) return;
    int p = idx % 49; int oc = (idx/49) & 63; int b = idx/(49*64);
    int y = p/7, xx = p%7;
    float acc = bias[oc];
    #pragma unroll
    for (int ci=0; ci<3; ci++){
        const float* xp = x + (b*3+ci)*64 + y*8 + xx;
        const float* wp = w + (oc*3+ci)*4;
        acc += xp[0]*wp[0] + xp[1]*wp[1] + xp[8]*wp[2] + xp[9]*wp[3];
    }
    g_h1[idx] = gelu_f(acc);
}

// ---------------- im2col fp32 ----------------
__global__ void __launch_bounds__(256) k_im2col_a(){
    int k = blockIdx.y;
    int n = blockIdx.x*256 + threadIdx.x;
    if (n >= 18432) return;
    int ic = k>>2, tap = k&3, dy = tap>>1, dx = tap&1;
    int b = n/36, p = n - b*36;
    int py = p/6, px = p - py*6;
    g_col[(size_t)k*18432 + n] = g_h1[((size_t)b*64+ic)*49 + (py+dy)*7 + (px+dx)];
}

__global__ void __launch_bounds__(256) k_im2col_b(int selSrc, int IPIX, int IW,
                                                  int OW, int OPIX, int Ntot){
    const float* src = g_selbuf(selSrc);
    int k = blockIdx.y;
    int n = blockIdx.x*256 + threadIdx.x;
    if (n >= Ntot) return;
    int ic = k>>2, tap = k&3, dy = tap>>1, dx = tap&1;
    int b = n/OPIX, p = n - b*OPIX;
    int py = p/OW, px = p - py*OW;
    g_col[(size_t)k*Ntot + n] = src[(size_t)ic*(NB*IPIX) + b*IPIX + (py+dy)*IW + (px+dx)];
}

// ---------------- fp32 SIMT GEMM (conv stack): 128x128x16, 8x8 micro ----------------
template<int GELU, int BIASM>
__global__ void __launch_bounds__(256) k_bgemm(const float* __restrict__ Aext,
                                               const float* __restrict__ bias,
                                               int M, int K, int N,
                                               int selB, int selC){
    const float* A = Aext;
    const float* B = g_selbuf(selB);
    float*       C = g_selbuf(selC);
    __shared__ float As[16][128];
    __shared__ float Bs[16][128];
    int tid = threadIdx.x;
    int n0 = blockIdx.x*128, m0 = blockIdx.y*128;
    int tx = tid&15, ty = tid>>4;
    int aR0 = tid>>2,        aC0 = (tid&3)*4;
    int aR1 = (tid+256)>>2,  aC1 = aC0;
    int bK0 = tid>>5,        bC0 = (tid&31)*4;
    int bK1 = (tid+256)>>5,  bC1 = bC0;

    float4 pa0, pa1, pb0, pb1;
    {
        int r0 = m0 + aR0, r1 = m0 + aR1;
        pa0 = (r0 < M) ? *(const float4*)&A[(size_t)r0*K + aC0] : make_float4(0.f,0.f,0.f,0.f);
        pa1 = (r1 < M) ? *(const float4*)&A[(size_t)r1*K + aC1] : make_float4(0.f,0.f,0.f,0.f);
        pb0 = *(const float4*)&B[(size_t)bK0*N + n0 + bC0];
        pb1 = *(const float4*)&B[(size_t)bK1*N + n0 + bC1];
    }
    float acc[8][8];
    #pragma unroll
    for (int u=0;u<8;u++)
        #pragma unroll
        for (int v=0;v<8;v++) acc[u][v]=0.f;

    for (int k0=0; k0<K; k0+=16){
        As[aC0+0][aR0]=pa0.x; As[aC0+1][aR0]=pa0.y; As[aC0+2][aR0]=pa0.z; As[aC0+3][aR0]=pa0.w;
        As[aC1+0][aR1]=pa1.x; As[aC1+1][aR1]=pa1.y; As[aC1+2][aR1]=pa1.z; As[aC1+3][aR1]=pa1.w;
        *(float4*)&Bs[bK0][bC0] = pb0;
        *(float4*)&Bs[bK1][bC1] = pb1;
        __syncthreads();
        int kn = k0 + 16;
        if (kn < K){
            int r0 = m0 + aR0, r1 = m0 + aR1;
            pa0 = (r0 < M) ? *(const float4*)&A[(size_t)r0*K + kn + aC0] : make_float4(0.f,0.f,0.f,0.f);
            pa1 = (r1 < M) ? *(const float4*)&A[(size_t)r1*K + kn + aC1] : make_float4(0.f,0.f,0.f,0.f);
            pb0 = *(const float4*)&B[(size_t)(kn+bK0)*N + n0 + bC0];
            pb1 = *(const float4*)&B[(size_t)(kn+bK1)*N + n0 + bC1];
        }
        #pragma unroll
        for (int kk=0; kk<16; kk++){
            float4 a40 = *(const float4*)&As[kk][ty*8];
            float4 a41 = *(const float4*)&As[kk][ty*8+4];
            float4 b40 = *(const float4*)&Bs[kk][tx*8];
            float4 b41 = *(const float4*)&Bs[kk][tx*8+4];
            float a_[8] = {a40.x,a40.y,a40.z,a40.w, a41.x,a41.y,a41.z,a41.w};
            float b_[8] = {b40.x,b40.y,b40.z,b40.w, b41.x,b41.y,b41.z,b41.w};
            #pragma unroll
            for (int u=0;u<8;u++)
                #pragma unroll
                for (int v=0;v<8;v++) acc[u][v] = fmaf(a_[u], b_[v], acc[u][v]);
        }
        __syncthreads();
    }
    #pragma unroll
    for (int u=0;u<8;u++){
        int m = m0 + ty*8 + u;
        if (m >= M) continue;
        float bm = BIASM ? bias[m] : 0.f;
        #pragma unroll
        for (int v=0;v<8;v++){
            int c = n0 + tx*8 + v;
            float val = acc[u][v] + (BIASM ? bm : bias[c]);
            if (GELU) val = gelu_f(val);
            C[(size_t)m*N + c] = val;
        }
    }
}

// ---------------- HMMA GEMM (MLP tail): fp16 in, fp32 accum, 128x128x32 ----------------
#define AS_LD 40   // 32 + 8 pad (halves)
#define BS_LD 136  // 128 + 8 pad
template<int GELU, int HEAD, int COUT16>
__global__ void __launch_bounds__(256) k_hgemm(const float* __restrict__ bias,
                                               float* __restrict__ Cext,
                                               int M, int K, int N,
                                               int selA, int offB, int selC){
    const __half* A = g_selh(selA);
    const __half* B = g_wh + offB;
    __shared__ __half As[128*AS_LD];
    __shared__ __half Bs[32*BS_LD];
    int tid = threadIdx.x;
    int wid = tid>>5, lane = tid&31;
    int n0 = blockIdx.x*128, m0 = blockIdx.y*128;
    int m0w = (wid>>1)*32, n0w = (wid&1)*64;

    int aR = tid>>2, aK8 = (tid&3)*8;
    int bK = tid>>4, bN8 = (tid&15)*8;

    uint4 pa0, pa1, pb0, pb1;
    {
        pa0 = *(const uint4*)&A[(size_t)(m0+aR)*K + aK8];
        pa1 = *(const uint4*)&A[(size_t)(m0+aR+64)*K + aK8];
        pb0 = *(const uint4*)&B[(size_t)bK*N + n0 + bN8];
        pb1 = *(const uint4*)&B[(size_t)(bK+16)*N + n0 + bN8];
    }

    float c[2][8][4];
    #pragma unroll
    for (int tm=0;tm<2;tm++)
        #pragma unroll
        for (int tn=0;tn<8;tn++)
            #pragma unroll
            for (int q=0;q<4;q++) c[tm][tn][q]=0.f;

    for (int k0=0; k0<K; k0+=32){
        *(uint4*)&As[aR*AS_LD + aK8]        = pa0;
        *(uint4*)&As[(aR+64)*AS_LD + aK8]   = pa1;
        *(uint4*)&Bs[bK*BS_LD + bN8]        = pb0;
        *(uint4*)&Bs[(bK+16)*BS_LD + bN8]   = pb1;
        __syncthreads();
        int kn = k0 + 32;
        if (kn < K){
            pa0 = *(const uint4*)&A[(size_t)(m0+aR)*K + kn + aK8];
            pa1 = *(const uint4*)&A[(size_t)(m0+aR+64)*K + kn + aK8];
            pb0 = *(const uint4*)&B[(size_t)(kn+bK)*N + n0 + bN8];
            pb1 = *(const uint4*)&B[(size_t)(kn+bK+16)*N + n0 + bN8];
        }
        #pragma unroll
        for (int ks=0; ks<2; ks++){
            unsigned a[2][4], bfr[8][2];
            #pragma unroll
            for (int tm=0;tm<2;tm++){
                const __half* ap = &As[(m0w + tm*16 + (lane&15))*AS_LD + ks*16 + ((lane>>4)<<3)];
                unsigned addr = (unsigned)__cvta_generic_to_shared(ap);
                asm volatile("ldmatrix.sync.aligned.m8n8.x4.shared.b16 {%0,%1,%2,%3}, [%4];"
                             : "=r"(a[tm][0]),"=r"(a[tm][1]),"=r"(a[tm][2]),"=r"(a[tm][3])
                             : "r"(addr));
            }
            #pragma unroll
            for (int tn=0;tn<8;tn++){
                const __half* bp = &Bs[(ks*16 + (lane&15))*BS_LD + n0w + tn*8];
                unsigned addr = (unsigned)__cvta_generic_to_shared(bp);
                asm volatile("ldmatrix.sync.aligned.m8n8.x2.trans.shared.b16 {%0,%1}, [%2];"
                             : "=r"(bfr[tn][0]),"=r"(bfr[tn][1])
                             : "r"(addr));
            }
            #pragma unroll
            for (int tm=0;tm<2;tm++)
                #pragma unroll
                for (int tn=0;tn<8;tn++){
                    asm volatile("mma.sync.aligned.m16n8k16.row.col.f32.f16.f16.f32 "
                                 "{%0,%1,%2,%3}, {%4,%5,%6,%7}, {%8,%9}, {%0,%1,%2,%3};"
                                 : "+f"(c[tm][tn][0]),"+f"(c[tm][tn][1]),
                                   "+f"(c[tm][tn][2]),"+f"(c[tm][tn][3])
                                 : "r"(a[tm][0]),"r"(a[tm][1]),"r"(a[tm][2]),"r"(a[tm][3]),
                                   "r"(bfr[tn][0]),"r"(bfr[tn][1]));
                }
        }
        __syncthreads();
    }

    __half* Ch = COUT16 ? g_selh(selC) : nullptr;
    int rbase = m0 + m0w + (lane>>2);
    int cbase = n0 + n0w + 2*(lane&3);
    #pragma unroll
    for (int tm=0;tm<2;tm++){
        #pragma unroll
        for (int hm=0; hm<2; hm++){
            int m = rbase + tm*16 + hm*8;
            #pragma unroll
            for (int tn=0;tn<8;tn++){
                int cc = cbase + tn*8;
                float v0 = c[tm][tn][hm*2+0] + bias[cc];
                float v1 = c[tm][tn][hm*2+1] + bias[cc+1];
                if (GELU){ v0 = gelu_f(v0); v1 = gelu_f(v1); }
                if (COUT16){
                    *(__half2*)&Ch[(size_t)m*N + cc] = __floats2half2_rn(v0, v1);
                } else if (HEAD){
                    Cext[(m>>2)*512 + cc*4     + (m&3)] = v0;
                    Cext[(m>>2)*512 + (cc+1)*4 + (m&3)] = v1;
                } else {
                    Cext[(size_t)m*N + cc]   = v0;
                    Cext[(size_t)m*N + cc+1] = v1;
                }
            }
        }
    }
}

// ---------------- squash ----------------
__global__ void __launch_bounds__(256) k_squash(){
    int e = blockIdx.x*256 + threadIdx.x;
    if (e >= NI*NB) return;
    int oc = e>>9, b = e&511;
    const float* src = &g_cp[(size_t)oc*8192 + b*16];
    float v[16];
    float nn = 0.f;
    #pragma unroll
    for (int p=0;p<16;p++){ v[p]=src[p]; nn += v[p]*v[p]; }
    float n = __fsqrt_rn(nn);
    float sc = (1.f - exp_inline(-n)) * __frcp_rn(n + 1e-8f);
    float* dst = &g_u[((size_t)b*NI+oc)*ND];
    #pragma unroll
    for (int p=0;p<16;p++) dst[p] = v[p]*sc;
}

// ---------------- einsum v2: persistent block per (half-batch, o) ----------------
__global__ void __launch_bounds__(384) k_einsum(const float* __restrict__ W){
    extern __shared__ float ush[];
    const int BUF = 4*96*20;
    int half = blockIdx.x;
    int o    = blockIdx.y;
    int tid  = threadIdx.x;
    int i = tid>>2, dq = tid&3;

    const float4* Wv = (const float4*)(W + ((size_t)(o*NI + i)*ND + dq*4)*ND);
    float4 wr[16];
    #pragma unroll
    for (int t=0;t<16;t++) wr[t]=Wv[t];

    int b_base = half*256;
    const float4* usrc = (const float4*)(g_u + (size_t)b_base*1536);
    int si = tid>>2, sk4 = (tid&3)*4;

    float4 pre[4];
    #pragma unroll
    for (int j=0;j<4;j++) pre[j] = usrc[j*384 + tid];
    {
        float* b0 = ush;
        #pragma unroll
        for (int j=0;j<4;j++) *(float4*)&b0[(j*96+si)*20 + sk4] = pre[j];
    }
    __syncthreads();

    for (int c=0; c<64; c++){
        const float* cur = ush + (c&1)*BUF;
        float*       nxt = ush + ((c+1)&1)*BUF;
        if (c < 63){
            const float4* s2 = usrc + (size_t)(c+1)*1536;
            #pragma unroll
            for (int j=0;j<4;j++) pre[j] = s2[j*384 + tid];
        }
        #pragma unroll
        for (int bb=0; bb<4; bb++){
            const float* ub = &cur[(bb*96+i)*20];
            float4 u0=*(const float4*)(ub), u1=*(const float4*)(ub+4),
                   u2=*(const float4*)(ub+8), u3=*(const float4*)(ub+12);
            float a0, a1, a2, a3;
            {
                float4 wa=wr[0], wb=wr[1], wc=wr[2], wd=wr[3];
                a0 = wa.x*u0.x + wa.y*u0.y + wa.z*u0.z + wa.w*u0.w
                   + wb.x*u1.x + wb.y*u1.y + wb.z*u1.z + wb.w*u1.w
                   + wc.x*u2.x + wc.y*u2.y + wc.z*u2.z + wc.w*u2.w
                   + wd.x*u3.x + wd.y*u3.y + wd.z*u3.z + wd.w*u3.w;
            }
            {
                float4 wa=wr[4], wb=wr[5], wc=wr[6], wd=wr[7];
                a1 = wa.x*u0.x + wa.y*u0.y + wa.z*u0.z + wa.w*u0.w
                   + wb.x*u1.x + wb.y*u1.y + wb.z*u1.z + wb.w*u1.w
                   + wc.x*u2.x + wc.y*u2.y + wc.z*u2.z + wc.w*u2.w
                   + wd.x*u3.x + wd.y*u3.y + wd.z*u3.z + wd.w*u3.w;
            }
            {
                float4 wa=wr[8], wb=wr[9], wc=wr[10], wd=wr[11];
                a2 = wa.x*u0.x + wa.y*u0.y + wa.z*u0.z + wa.w*u0.w
                   + wb.x*u1.x + wb.y*u1.y + wb.z*u1.z + wb.w*u1.w
                   + wc.x*u2.x + wc.y*u2.y + wc.z*u2.z + wc.w*u2.w
                   + wd.x*u3.x + wd.y*u3.y + wd.z*u3.z + wd.w*u3.w;
            }
            {
                float4 wa=wr[12], wb=wr[13], wc=wr[14], wd=wr[15];
                a3 = wa.x*u0.x + wa.y*u0.y + wa.z*u0.z + wa.w*u0.w
                   + wb.x*u1.x + wb.y*u1.y + wb.z*u1.z + wb.w*u1.w
                   + wc.x*u2.x + wc.y*u2.y + wc.z*u2.z + wc.w*u2.w
                   + wd.x*u3.x + wd.y*u3.y + wd.z*u3.z + wd.w*u3.w;
            }
            __half2 p0 = __floats2half2_rn(a0, a1);
            __half2 p1 = __floats2half2_rn(a2, a3);
            int b = b_base + c*4 + bb;
            size_t base = (((size_t)b*NO + o)*NI + i)*ND + dq*4;
            *(__half2*)&g_uhat[base]     = p0;
            *(__half2*)&g_uhat[base + 2] = p1;
        }
        if (c < 63){
            #pragma unroll
            for (int j=0;j<4;j++) *(float4*)&nxt[(j*96+si)*20 + sk4] = pre[j];
        }
        __syncthreads();
    }
}

// ---------------- fused routing + peaks ----------------
__global__ void __launch_bounds__(512) k_routefuse(const float* __restrict__ caps_b,
                                                   float* __restrict__ d_out){
    extern __shared__ float sm[];
    float* bm  = sm;
    float* mx  = sm + 17376;
    float* inv = sm + 17472;
    float* red = sm + 17568;
    float* len = sm + 17952;
    float* pk  = sm + 18144;
    __shared__ float s_sum;
    int b = blockIdx.x;
    int t = threadIdx.x;
    for (int e=t; e<BOI; e+=512) bm[e] = caps_b[e];
    if (t < 192) len[t] = 0.f;
    __syncthreads();
    int wid = t>>5, lane = t&31;
    int i0 = lane*3;
    for (int iter=0; iter<3; iter++){
        if (t < 384){
            int i = t % 96, g = t / 96;
            float m = -1e30f;
            for (int o=g; o<NO; o+=4) m = fmaxf(m, bm[o*96+i]);
            red[g*96+i] = m;
        }
        __syncthreads();
        if (t < 96) mx[t] = fmaxf(fmaxf(red[t], red[96+t]), fmaxf(red[192+t], red[288+t]));
        __syncthreads();
        if (t < 384){
            int i = t % 96, g = t / 96;
            float m = mx[i];
            float s = 0.f;
            for (int o=g; o<NO; o+=4) s += __expf(bm[o*96+i] - m);
            red[g*96+i] = s;
        }
        __syncthreads();
        if (t < 96) inv[t] = __frcp_rn(red[t]+red[96+t]+red[192+t]+red[288+t]);
        __syncthreads();
        int last = (iter==2);
        for (int o=wid; o<NO; o+=16){
            const float4* hp = (const float4*)(g_uhat + ((size_t)b*NO + o)*1536 + lane*48);
            float hf[48];
            #pragma unroll
            for (int q=0;q<6;q++){
                float4 r4 = hp[q];
                const __half2* hh = (const __half2*)&r4;
                #pragma unroll
                for (int x=0;x<4;x++){
                    float2 f = __half22float2(hh[x]);
                    hf[q*8+x*2]   = f.x;
                    hf[q*8+x*2+1] = f.y;
                }
            }
            float c0 = __expf(bm[o*96+i0  ] - mx[i0  ]) * inv[i0  ];
            float c1 = __expf(bm[o*96+i0+1] - mx[i0+1]) * inv[i0+1];
            float c2 = __expf(bm[o*96+i0+2] - mx[i0+2]) * inv[i0+2];
            float S[16];
            #pragma unroll
            for (int d=0;d<16;d++)
                S[d] = c0*hf[d] + c1*hf[16+d] + c2*hf[32+d];
            #pragma unroll
            for (int off=16; off>0; off>>=1){
                #pragma unroll
                for (int d=0;d<16;d++) S[d] += __shfl_xor_sync(0xffffffffu, S[d], off);
            }
            float nn = 0.f;
            #pragma unroll
            for (int d=0;d<16;d++) nn += S[d]*S[d];
            float n = __fsqrt_rn(nn);
            float sc = (1.f - __expf(-n)) * __frcp_rn(n + 1e-8f);
            if (!last){
                float d0=0.f, d1=0.f, d2=0.f;
                #pragma unroll
                for (int d=0;d<16;d++){
                    float vd = S[d]*sc;
                    d0 = fmaf(vd, hf[d],    d0);
                    d1 = fmaf(vd, hf[16+d], d1);
                    d2 = fmaf(vd, hf[32+d], d2);
                }
                bm[o*96+i0  ] += d0;
                bm[o*96+i0+1] += d1;
                bm[o*96+i0+2] += d2;
            } else {
                if (lane < 16) g_x[((size_t)b*NO+o)*ND + lane] = S[lane]*sc;
                if (lane == 0) len[o] = n*sc;
            }
        }
        __syncthreads();
    }
    if (t==0){
        float s=0.f;
        for (int o=0;o<NO;o++) s+=len[o];
        s_sum = s + 1e-8f;
    }
    __syncthreads();
    if (t < NO) len[t] = len[t] / s_sum;
    __syncthreads();
    if (t < NO){
        float m = -1e30f;
        #pragma unroll
        for (int dd=-5; dd<=5; dd++){
            int oo = t+dd;
            if (oo>=0 && oo<NO) m = fmaxf(m, len[oo]);
        }
        pk[t] = (len[t]==m) ? len[t] : 0.f;
        d_out[NB*128*4 + b*NO + t] = len[t];
    } else if (t < 192) pk[t] = 0.f;
    __syncthreads();
    if (t==0){
        int i0s, i1s, i2s, i3s;
        {
            float bv=-1.f; int bi=0;
            for (int o=0;o<NO;o++){ float v=pk[o]; if (v>bv){ bv=v; bi=o; } }
            i0s=bi; pk[bi]=-2.f;
        }
        {
            float bv=-1.f; int bi=0;
            for (int o=0;o<NO;o++){ float v=pk[o]; if (v>bv){ bv=v; bi=o; } }
            i1s=bi; pk[bi]=-2.f;
        }
        {
            float bv=-1.f; int bi=0;
            for (int o=0;o<NO;o++){ float v=pk[o]; if (v>bv){ bv=v; bi=o; } }
            i2s=bi; pk[bi]=-2.f;
        }
        {
            float bv=-1.f; int bi=0;
            for (int o=0;o<NO;o++){ float v=pk[o]; if (v>bv){ bv=v; bi=o; } }
            i3s=bi;
        }
        int tmp;
        if (i0s>i1s){tmp=i0s;i0s=i1s;i1s=tmp;}
        if (i2s>i3s){tmp=i2s;i2s=i3s;i3s=tmp;}
        if (i0s>i2s){tmp=i0s;i0s=i2s;i2s=tmp;}
        if (i1s>i3s){tmp=i1s;i1s=i3s;i3s=tmp;}
        if (i1s>i2s){tmp=i1s;i1s=i2s;i2s=tmp;}
        g_idx[b*4+0]=i0s; g_idx[b*4+1]=i1s; g_idx[b*4+2]=i2s; g_idx[b*4+3]=i3s;
    }
}

// ---------------- fc1 (sparse gather GEMV) -> gelu -> g_a1h fp16 ----------------
__global__ void __launch_bounds__(256) k_fc1(const float* __restrict__ w,
                                             const float* __restrict__ bias){
    int j = blockIdx.x*256 + threadIdx.x;
    int row = blockIdx.y;
    if (j >= 1024) return;
    int b = row>>2, k = row&3;
    int id = g_idx[b*4+k];
    const float* xv = &g_x[(b*NO+id)*ND];
    float acc = bias[j];
    #pragma unroll
    for (int d=0; d<16; d++) acc += xv[d]*w[(id*16+d)*1024 + j];
    g_a1h[row*1024 + j] = __float2half(gelu_f(acc));
}

// ---------------- launch ----------------
extern "C" void kernel_launch(void* const* d_in, const int* in_sizes, int n_in,
                              void* d_out, int out_size){
    const float* scm     = (const float*)d_in[0];
    const float* w1 = (const float*)d_in[2];  const float* b1 = (const float*)d_in[3];
    const float* w2 = (const float*)d_in[4];  const float* b2 = (const float*)d_in[5];
    const float* w3 = (const float*)d_in[6];  const float* b3 = (const float*)d_in[7];
    const float* pw = (const float*)d_in[8];  const float* pb = (const float*)d_in[9];
    const float* capsW = (const float*)d_in[10];
    const float* capsB = (const float*)d_in[11];
    const float* f1w = (const float*)d_in[12]; const float* f1b = (const float*)d_in[13];
    const float* f2w = (const float*)d_in[14]; const float* f2b = (const float*)d_in[15];
    const float* f3w = (const float*)d_in[16]; const float* f3b = (const float*)d_in[17];
    const float* f4w = (const float*)d_in[18]; const float* f4b = (const float*)d_in[19];
    const float* f5w = (const float*)d_in[20]; const float* f5b = (const float*)d_in[21];
    const float* hw  = (const float*)d_in[22]; const float* hb  = (const float*)d_in[23];
    float* out = (float*)d_out;

    const int einsum_smem = 2*4*NI*20*4;  // 61440 B
    const int route_smem  = 120*1024;
    cudaFuncSetAttribute(k_einsum,    cudaFuncAttributeMaxDynamicSharedMemorySize, einsum_smem);
    cudaFuncSetAttribute(k_routefuse, cudaFuncAttributeMaxDynamicSharedMemorySize, route_smem);

    // fp16 MLP weight conversions
    k_tohalf<<<(786432+255)/256, 256>>>(f2w, OFF_F2, 786432);
    k_tohalf<<<(393216+255)/256, 256>>>(f3w, OFF_F3, 393216);
    k_tohalf<<<(262144+255)/256, 256>>>(f4w, OFF_F4, 262144);
    k_tohalf<<<(131072+255)/256, 256>>>(f5w, OFF_F5, 131072);
    k_tohalf<<<(32768+255)/256, 256>>>(hw,  OFF_HW, 32768);

    // conv stack as im2col + fp32 SIMT GEMM (upstream of argmax: keep fp32)
    k_conv1<<<(NB*64*49 + 255)/256, 256>>>(scm, w1, b1);
    k_im2col_a<<<dim3(72, 256), 256>>>();
    k_bgemm<1,1><<<dim3(144, 1), 256>>>(w2, b2, 128, 256, 18432, 0, 1);
    k_im2col_b<<<dim3(50, 512), 256>>>(1, 36, 6, 5, 25, 12800);
    k_bgemm<1,1><<<dim3(100, 2), 256>>>(w3, b3, 256, 512, 12800, 0, 2);
    k_im2col_b<<<dim3(32, 1024), 256>>>(2, 25, 5, 4, 16, 8192);
    k_bgemm<0,1><<<dim3(64, 1), 256>>>(pw, pb, 96, 1024, 8192, 0, 3);
    k_squash<<<(NI*NB + 255)/256, 256>>>();

    // capsule layer
    k_einsum<<<dim3(2, NO), 384, einsum_smem>>>(capsW);
    k_routefuse<<<NB, 512, route_smem>>>(capsB, out);

    // MLP tail in fp16 HMMA (downstream of argmax)
    k_fc1<<<dim3(4, 2048), 256>>>(f1w, f1b);
    k_hgemm<1,0,1><<<dim3(6, 16), 256>>>(f2b, nullptr, 2048, 1024, 768, 4, OFF_F2, 5);
    k_hgemm<1,0,1><<<dim3(4, 16), 256>>>(f3b, nullptr, 2048, 768,  512, 5, OFF_F3, 6);
    k_hgemm<1,0,1><<<dim3(4, 16), 256>>>(f4b, nullptr, 2048, 512,  512, 6, OFF_F4, 7);
    k_hgemm<1,0,1><<<dim3(2, 16), 256>>>(f5b, nullptr, 2048, 512,  256, 7, OFF_F5, 8);
    k_hgemm<0,1,0><<<dim3(1, 16), 256>>>(hb,  out,     2048, 256,  128, 8, OFF_HW, -1);
    (void)in_sizes; (void)n_in; (void)out_size;
}